// round 15
// baseline (speedup 1.0000x reference)
#include <cuda_runtime.h>
#include <cuda_fp16.h>

#define NEXP 4
#define MT 128
#define SEG_CAP 32768
#define ASH 40                    // A smem stride (halves), 80B rows, 16B-aligned
#define BSH 40                    // B smem stride (halves)
#define A_TILE_H (128 * ASH)
#define B_TILE_H (128 * BSH)
#define NSTAGE 4

__device__ int g_fill[NEXP];
__device__ int g_fill_ro[NEXP];
__device__ int g_done;
__device__ int g_perm[NEXP * SEG_CAP];
// [e][ws][n][k] fp16 RN, 0.5 folded for ws>=4
__device__ __align__(16) __half g_wimg[4 * 8 * 128 * 128];

// ---------------- helpers ----------------
__device__ __forceinline__ unsigned smem_u32(const void* p) {
    unsigned a;
    asm("{ .reg .u64 t; cvta.to.shared.u64 t, %1; cvt.u32.u64 %0, t; }" : "=r"(a) : "l"(p));
    return a;
}
__device__ __forceinline__ void cp16(unsigned dst, const void* src) {
    asm volatile("cp.async.cg.shared.global [%0], [%1], 16;" :: "r"(dst), "l"(src));
}
__device__ __forceinline__ void ldm4(unsigned* r, unsigned addr) {
    asm volatile("ldmatrix.sync.aligned.m8n8.x4.shared.b16 {%0,%1,%2,%3}, [%4];"
        : "=r"(r[0]), "=r"(r[1]), "=r"(r[2]), "=r"(r[3]) : "r"(addr));
}
__device__ __forceinline__ void mma_f16(float* d, const unsigned* a, const unsigned* b) {
    asm volatile(
        "mma.sync.aligned.m16n8k16.row.col.f32.f16.f16.f32 "
        "{%0,%1,%2,%3}, {%4,%5,%6,%7}, {%8,%9}, {%0,%1,%2,%3};"
        : "+f"(d[0]), "+f"(d[1]), "+f"(d[2]), "+f"(d[3])
        : "r"(a[0]), "r"(a[1]), "r"(a[2]), "r"(a[3]), "r"(b[0]), "r"(b[1]));
}

// ---------------- fused prep ----------------
__global__ void __launch_bounds__(256)
fused_prep_kernel(const float* __restrict__ W, const int* __restrict__ id,
                  int nb, int nsb) {
    __shared__ union {
        struct { int c[NEXP]; int base[NEXP]; } sc;
        float tr[32][129];
    } u;
    int bx = blockIdx.x;
    int tid = threadIdx.x;
    if (bx < nsb) {
        if (tid < NEXP) u.sc.c[tid] = 0;
        __syncthreads();
        int i = bx * 256 + tid;
        int e = 0, lp = 0;
        if (i < nb) { e = id[i] & 3; lp = atomicAdd(&u.sc.c[e], 1); }
        __syncthreads();
        if (tid < NEXP) u.sc.base[tid] = atomicAdd(&g_fill[tid], u.sc.c[tid]);
        __syncthreads();
        if (i < nb) g_perm[e * SEG_CAP + u.sc.base[e] + lp] = i;
        __syncthreads();
        if (tid == 0) {
            __threadfence();
            if (atomicAdd(&g_done, 1) == nsb - 1) {
#pragma unroll
                for (int q = 0; q < NEXP; ++q) {
                    g_fill_ro[q] = g_fill[q];
                    g_fill[q] = 0;
                }
                g_done = 0;
                __threadfence();
            }
        }
    } else {
        int t  = bx - nsb;        // 0..127
        int nc = t & 3;
        int ws = (t >> 2) & 7;
        int e  = t >> 5;
        float scale = (ws >= 4) ? 0.5f : 1.0f;
        const float* src = W + (size_t)e * 131072 + ws * 16384 + nc * 32;
        int tn = tid & 31;
        int tk = tid >> 5;
#pragma unroll
        for (int p = 0; p < 16; ++p) {
            int k = p * 8 + tk;
            u.tr[tn][k] = src[k * 128 + tn] * scale;
        }
        __syncthreads();
        __half* dst = g_wimg + (size_t)((e * 8 + ws) * 128 + nc * 32) * 128;
        int wk = tid & 127;
        int wn = tid >> 7;
#pragma unroll
        for (int p = 0; p < 16; ++p) {
            int n = p * 2 + wn;
            dst[n * 128 + wk] = __float2half_rn(u.tr[n][wk]);
        }
    }
}

// ---------------- fp16 mma.sync grouped GEMM ----------------
// grid: bx = tile*4 + kblk (kblk fastest -> same-tile CTAs co-resident, X L2 reuse)
// CTA 128x128, 256 threads, 8 warps, warp tile 32x64. 4-stage pipeline.
__global__ void __launch_bounds__(256, 2)
gemm_kernel(const float* __restrict__ X, float* __restrict__ Y) {
    extern __shared__ __half smh[];
    __half* Ah = smh;                               // [4][A_TILE_H]
    __half* Bh = smh + NSTAGE * A_TILE_H;           // [4][B_TILE_H]
    int* s_row = (int*)(smh + NSTAGE * (A_TILE_H + B_TILE_H));

    const int tid = threadIdx.x;
    const int kblk = blockIdx.x & 3;
    const int bt = blockIdx.x >> 2;

    // tile -> (expert, local tile) from snapshot
    int f0 = g_fill_ro[0], f1 = g_fill_ro[1], f2 = g_fill_ro[2], f3 = g_fill_ro[3];
    int t0 = (f0 + 127) >> 7, t1 = (f1 + 127) >> 7, t2 = (f2 + 127) >> 7;
    int p1 = t0, p2 = t0 + t1, p3 = p2 + t2, p4 = p3 + ((f3 + 127) >> 7);
    if (bt >= p4) return;
    int e, lt, fe;
    if (bt < p1)      { e = 0; lt = bt;      fe = f0; }
    else if (bt < p2) { e = 1; lt = bt - p1; fe = f1; }
    else if (bt < p3) { e = 2; lt = bt - p2; fe = f2; }
    else              { e = 3; lt = bt - p3; fe = f3; }

    if (tid < 128) {
        int gi = lt * MT + tid;
        s_row[tid] = (gi < fe) ? g_perm[e * SEG_CAP + gi] : -1;
    }
    __syncthreads();

    const int a0 = kblk, a1 = (kblk + 3) & 3;
    const int ws0 = kblk, ws1 = 4 + a1;

    // A staging: 4 passes, row j*32 + t8, 16B (4 f32) at slot sv
    const int sv = tid & 7;
    const int t8 = tid >> 3;       // 0..31
    const float* pX[4];
#pragma unroll
    for (int j = 0; j < 4; ++j) {
        int r = s_row[j * 32 + t8];
        pX[j] = X + (size_t)(r < 0 ? 0 : r) * 512 + sv * 4;
    }
    // B staging: thread covers half an n-row (32B) per chunk
    const int bn = tid >> 1;             // 0..127
    const int bs = (tid & 1) * 16;       // halves
    const __half* pB = g_wimg + ((size_t)(e * 8) * 128 + bn) * 128 + bs;
    const unsigned AbaseU = smem_u32(Ah);
    const unsigned BbaseU = smem_u32(Bh);
    const unsigned bB0 = BbaseU + (bn * BSH + bs) * 2;

    float4 v[4];
    auto ldA = [&](int kc) {
        int cb = (kc < 4) ? (a0 * 128 + kc * 32) : (a1 * 128 + (kc - 4) * 32);
#pragma unroll
        for (int j = 0; j < 4; ++j) v[j] = *(const float4*)(pX[j] + cb);
    };
    auto stsA = [&](int buf) {
        __half* dst0 = Ah + buf * A_TILE_H + t8 * ASH + sv * 4;
#pragma unroll
        for (int j = 0; j < 4; ++j) {
            __half2 h0 = __floats2half2_rn(v[j].x, v[j].y);
            __half2 h1 = __floats2half2_rn(v[j].z, v[j].w);
            uint2 u2 = make_uint2(*(unsigned*)&h0, *(unsigned*)&h1);
            *(uint2*)(dst0 + j * (32 * ASH)) = u2;
        }
    };
    auto cpB = [&](int kc, int buf) {
        const __half* src = pB + ((kc < 4) ? ws0 : ws1) * 16384 + (kc & 3) * 32;
        unsigned d = bB0 + buf * (B_TILE_H * 2);
        cp16(d, src);
        cp16(d + 16, src + 8);
        asm volatile("cp.async.commit_group;" ::: "memory");
    };

    // prologue: fully stage chunks 0,1,2; load chunk 3 into regs
    ldA(0); stsA(0); cpB(0, 0);
    ldA(1); stsA(1); cpB(1, 1);
    ldA(2); stsA(2); cpB(2, 2);
    ldA(3);

    const int lane = tid & 31, warp = tid >> 5;
    const int m0 = (warp & 3) * 32;
    const int n0 = (warp >> 2) * 64;
    const int qr = lane >> 2, qc = lane & 3;

    // ldmatrix lane offsets (bytes)
    const unsigned aLaneOff = ((m0 + (lane & 15)) * ASH + (lane >> 4) * 8) * 2;
    const unsigned bLaneOff =
        ((n0 + (lane >> 4) * 8 + (lane & 7)) * BSH + ((lane >> 3) & 1) * 8) * 2;

    float acc[2][8][4];
#pragma unroll
    for (int mt = 0; mt < 2; ++mt)
#pragma unroll
        for (int nt = 0; nt < 8; ++nt)
#pragma unroll
            for (int q = 0; q < 4; ++q) acc[mt][nt][q] = 0.f;

#pragma unroll 1
    for (int kc = 0; kc < 8; ++kc) {
        int buf = kc & 3;
        // own chunk-kc copy group complete; up to 2 newer groups in flight
        if (kc <= 5)      asm volatile("cp.async.wait_group 2;" ::: "memory");
        else if (kc == 6) asm volatile("cp.async.wait_group 1;" ::: "memory");
        else              asm volatile("cp.async.wait_group 0;" ::: "memory");
        __syncthreads();   // publishes chunk-kc copies; compute kc-1 done
        if (kc + 3 < 8) {
            int sb = (kc + 3) & 3;            // last read at chunk kc-1
            stsA(sb);                         // v holds chunk kc+3 (A)
            cpB(kc + 3, sb);
        }
        if (kc + 4 < 8) ldA(kc + 4);          // LDG hidden across compute

        const unsigned aB = AbaseU + buf * (A_TILE_H * 2) + aLaneOff;
        const unsigned bB = BbaseU + buf * (B_TILE_H * 2) + bLaneOff;
#pragma unroll
        for (int ks = 0; ks < 2; ++ks) {
            unsigned af[2][4];
            ldm4(af[0], aB + ks * 32);
            ldm4(af[1], aB + ks * 32 + 16 * ASH * 2);
            unsigned bf[8][2];
#pragma unroll
            for (int p = 0; p < 4; ++p) {
                unsigned r4[4];
                ldm4(r4, bB + ks * 32 + p * (16 * BSH * 2));
                bf[2 * p][0] = r4[0]; bf[2 * p][1] = r4[1];
                bf[2 * p + 1][0] = r4[2]; bf[2 * p + 1][1] = r4[3];
            }
#pragma unroll
            for (int mt = 0; mt < 2; ++mt)
#pragma unroll
                for (int nt = 0; nt < 8; ++nt)
                    mma_f16(acc[mt][nt], af[mt], bf[nt]);
        }
    }

    // epilogue: perm-scattered float2 stores
#pragma unroll
    for (int mt = 0; mt < 2; ++mt) {
        int gr0 = s_row[m0 + mt * 16 + qr];
        int gr1 = s_row[m0 + mt * 16 + qr + 8];
        float* y0 = (gr0 >= 0) ? (Y + (size_t)gr0 * 512 + kblk * 128) : 0;
        float* y1 = (gr1 >= 0) ? (Y + (size_t)gr1 * 512 + kblk * 128) : 0;
#pragma unroll
        for (int nt = 0; nt < 8; ++nt) {
            int col = n0 + nt * 8 + qc * 2;
            if (y0) *(float2*)(y0 + col) = make_float2(acc[mt][nt][0], acc[mt][nt][1]);
            if (y1) *(float2*)(y1 + col) = make_float2(acc[mt][nt][2], acc[mt][nt][3]);
        }
    }
}

// ---------------- launcher ----------------
extern "C" void kernel_launch(void* const* d_in, const int* in_sizes, int n_in,
                              void* d_out, int out_size) {
    const float* X  = (const float*)d_in[0];
    const float* W  = (const float*)d_in[1];
    const int*   ID = (const int*)d_in[2];
    float* Y = (float*)d_out;

    int nb = in_sizes[2];
    int nsb = (nb + 255) / 256;
    int maxTiles = (nb + MT - 1) / MT + NEXP;

    int smemBytes = NSTAGE * (A_TILE_H + B_TILE_H) * 2 + 512;   // 82432
    cudaFuncSetAttribute(gemm_kernel,
                         cudaFuncAttributeMaxDynamicSharedMemorySize, smemBytes);

    fused_prep_kernel<<<nsb + 128, 256>>>(W, ID, nb, nsb);
    gemm_kernel<<<maxTiles * 4, 256, smemBytes>>>(X, Y);
}